// round 2
// baseline (speedup 1.0000x reference)
#include <cuda_runtime.h>
#include <math.h>

// x[B=1024][T=8][V=4][D=8] fp32. Series (v,t) packed to g_xs[(v*8+t)][b][d].
// M = 1020. 28 pairs p=(v, t>=1); target series = (v,0).
#define B_N   1024
#define M_N   1020
#define RS    1024
#define N_PAIR 28

__device__ float g_xs [32 * B_N * 8];     // packed series, 1 MB
__device__ float g_E  [4  * B_N * RS];    // cheb8 matrices of the 4 target series (16.8 MB)
__device__ float g_WC [4  * M_N * RS];    // dC
__device__ float g_WAC[4  * M_N * RS];    // dAC = max(dC, E[i+4][j+4])
__device__ float g_part[N_PAIR * 256];
__device__ float g_psi[1040];

// ---------------- digamma table (double-precision series; deterministic) -------------------
__global__ void psi_kernel() {
    int k = blockIdx.x * blockDim.x + threadIdx.x;
    if (k >= 1040) return;
    if (k == 0) { g_psi[0] = 0.f; return; }
    double s = 0.0;
    #pragma unroll
    for (int m = 0; m < 8; m++) s += 1.0 / (double)(k + m);
    double y = (double)k + 8.0;
    double inv = 1.0 / y, inv2 = inv * inv;
    double ps = log(y) - 0.5 * inv
              - inv2 * (1.0 / 12.0 - inv2 * (1.0 / 120.0 - inv2 * (1.0 / 252.0)));
    g_psi[k] = (float)(ps - s);
}

// ---------------- pack x -> per-series contiguous layout -----------------------------------
__global__ void pack_kernel(const float* __restrict__ x) {
    int o = blockIdx.x * 256 + threadIdx.x;       // float4 index, 65536 total
    int s = o >> 11;
    int r = o & 2047;
    int b = r >> 1, h = r & 1;
    int v = s >> 3, t = s & 7;
    ((float4*)g_xs)[o] = ((const float4*)x)[b * 64 + t * 8 + v * 2 + h];
}

// ---------------- E[v][i][j] = cheb8 of target series (v,0) --------------------------------
__global__ void e_kernel() {
    __shared__ float xs[B_N * 12];
    int v = blockIdx.y;
    const float4* src = (const float4*)(g_xs + (size_t)(v * 8) * (B_N * 8));
    for (int idx = threadIdx.x; idx < 2048; idx += blockDim.x) {
        float4 q = src[idx];
        int b = idx >> 1, h = idx & 1;
        *(float4*)&xs[b * 12 + h * 4] = q;
    }
    __syncthreads();
    int warp = threadIdx.x >> 5, lane = threadIdx.x & 31;
    float* Eo = g_E + (size_t)v * (B_N * RS);
    for (int iw = 0; iw < 8; iw++) {
        int i = blockIdx.x * 64 + iw * 8 + warp;
        float4 xa = *(const float4*)&xs[i * 12];
        float4 xb = *(const float4*)&xs[i * 12 + 4];
        float* orow = Eo + (size_t)i * RS;
        for (int it = 0; it < 8; it++) {
            int j4 = it * 128 + lane * 4;
            float res[4];
            #pragma unroll
            for (int c = 0; c < 4; c++) {
                int j = j4 + c;
                float4 ya = *(const float4*)&xs[j * 12];
                float4 yb = *(const float4*)&xs[j * 12 + 4];
                float m;
                m =          fabsf(xa.x - ya.x);
                m = fmaxf(m, fabsf(xa.y - ya.y));
                m = fmaxf(m, fabsf(xa.z - ya.z));
                m = fmaxf(m, fabsf(xa.w - ya.w));
                m = fmaxf(m, fabsf(xb.x - yb.x));
                m = fmaxf(m, fabsf(xb.y - yb.y));
                m = fmaxf(m, fabsf(xb.z - yb.z));
                m = fmaxf(m, fabsf(xb.w - yb.w));
                res[c] = m;
            }
            *(float4*)(orow + j4) = make_float4(res[0], res[1], res[2], res[3]);
        }
    }
}

// ---------------- WC / WAC from E (only 4 target series) -----------------------------------
__global__ void w_kernel() {
    int v = blockIdx.y;
    int warp = threadIdx.x >> 5, lane = threadIdx.x & 31;
    int i = blockIdx.x * 8 + warp;
    if (i >= M_N) return;
    const float* E = g_E + (size_t)v * (B_N * RS);
    float* outC  = g_WC  + (size_t)v * (M_N * RS) + (size_t)i * RS;
    float* outAC = g_WAC + (size_t)v * (M_N * RS) + (size_t)i * RS;
    for (int it = 0; it < 8; it++) {
        int j4 = it * 128 + lane * 4;
        if (j4 >= M_N) continue;
        float o[4] = {-1e30f, -1e30f, -1e30f, -1e30f};
        #pragma unroll
        for (int r = 0; r < 4; r++) {
            const float* row = E + (size_t)(i + r) * RS + j4;
            float e8[8];
            float4 qa = *(const float4*)row;
            e8[0] = qa.x; e8[1] = qa.y; e8[2] = qa.z; e8[3] = qa.w;
            if (r > 0) {
                float4 qb = *(const float4*)(row + 4);
                e8[4] = qb.x; e8[5] = qb.y; e8[6] = qb.z; e8[7] = qb.w;
            }
            #pragma unroll
            for (int c = 0; c < 4; c++)
                o[c] = fmaxf(o[c], e8[r + c]);
        }
        *(float4*)(outC + j4) = make_float4(o[0], o[1], o[2], o[3]);
        float4 qa4 = *(const float4*)(E + (size_t)(i + 4) * RS + j4 + 4);
        *(float4*)(outAC + j4) = make_float4(
            fmaxf(o[0], qa4.x), fmaxf(o[1], qa4.y),
            fmaxf(o[2], qa4.z), fmaxf(o[3], qa4.w));
    }
}

// ---------------- fused: WB-from-x + kNN + counts ------------------------------------------
__device__ __forceinline__ void ins3(float v, float& t0, float& t1, float& t2) {
    if (v < t2) {
        if (v < t1) {
            t2 = t1;
            if (v < t0) { t1 = t0; t0 = v; } else t1 = v;
        } else t2 = v;
    }
}

__global__ void __launch_bounds__(128) te_kernel() {
    // dynamic smem: [0:8192) series S (1024 x 8 floats), [8192:12288) per-warp WB rows
    extern __shared__ float sh[];
    __shared__ float s_red[4];
    float4* S4 = (float4*)sh;
    int lane = threadIdx.x & 31, warp = threadIdx.x >> 5;
    float* swb = sh + 8192 + warp * 1024;

    int p = blockIdx.y, v = p / 7, t = 1 + p % 7;
    const float4* src = (const float4*)(g_xs + (size_t)(v * 8 + t) * (B_N * 8));
    for (int idx = threadIdx.x; idx < 2048; idx += 128) S4[idx] = src[idx];
    __syncthreads();

    int i = blockIdx.x * 4 + warp;                 // 255*4 = 1020 rows, all valid
    const float* wac_row = g_WAC + (size_t)v * (M_N * RS) + (size_t)i * RS;
    const float* wc_row  = g_WC  + (size_t)v * (M_N * RS) + (size_t)i * RS;

    float4 xa[4][2];
    #pragma unroll
    for (int r = 0; r < 4; r++) {
        xa[r][0] = S4[(i + r) * 2];
        xa[r][1] = S4[(i + r) * 2 + 1];
    }

    bool f1 = lane <= 30, f2 = lane <= 29, f3 = lane <= 28;
    float t0 = 1e30f, t1 = 1e30f, t2 = 1e30f;
    float carry = 0.f;

    for (int k = 0; k < 32; k++) {
        float4 ya = S4[(k * 32 + lane) * 2];
        float4 yb = S4[(k * 32 + lane) * 2 + 1];
        float vv[4];
        #pragma unroll
        for (int r = 0; r < 4; r++) {
            float m;
            m =          fabsf(xa[r][0].x - ya.x);
            m = fmaxf(m, fabsf(xa[r][0].y - ya.y));
            m = fmaxf(m, fabsf(xa[r][0].z - ya.z));
            m = fmaxf(m, fabsf(xa[r][0].w - ya.w));
            m = fmaxf(m, fabsf(xa[r][1].x - yb.x));
            m = fmaxf(m, fabsf(xa[r][1].y - yb.y));
            m = fmaxf(m, fabsf(xa[r][1].z - yb.z));
            m = fmaxf(m, fabsf(xa[r][1].w - yb.w));
            vv[r] = m;
        }
        // diagonal window: element j needs v_r from the lane holding row j+r
        float s1 = __shfl_sync(0xffffffffu, vv[1], (lane + 1) & 31);
        float s2 = __shfl_sync(0xffffffffu, vv[2], (lane + 2) & 31);
        float s3 = __shfl_sync(0xffffffffu, vv[3], (lane + 3) & 31);
        float mcur = vv[0], mprev = carry;
        if (f1) mcur = fmaxf(mcur, s1); else mprev = fmaxf(mprev, s1);
        if (f2) mcur = fmaxf(mcur, s2); else mprev = fmaxf(mprev, s2);
        if (f3) mcur = fmaxf(mcur, s3); else mprev = fmaxf(mprev, s3);
        carry = mcur;
        int   jf  = f3 ? (k * 32 + lane) : ((k - 1) * 32 + lane);
        float wbv = f3 ? mcur : mprev;
        if (f3 || k > 0) {
            swb[jf] = wbv;                          // same lane rereads it in pass 2
            if (jf < M_N && jf != i) {
                float dj = fmaxf(wbv, __ldg(wac_row + jf));
                ins3(dj, t0, t1, t2);
            }
        }
    }
    // merge per-lane top-3 -> eps (3rd NN radius)
    #pragma unroll
    for (int off = 16; off > 0; off >>= 1) {
        float o0 = __shfl_xor_sync(0xffffffffu, t0, off);
        float o1 = __shfl_xor_sync(0xffffffffu, t1, off);
        float o2 = __shfl_xor_sync(0xffffffffu, t2, off);
        ins3(o0, t0, t1, t2); ins3(o1, t0, t1, t2); ins3(o2, t0, t1, t2);
    }
    float eps = t2;

    int nA = 0, nB = 0, nC = 0;
    #pragma unroll
    for (int k = 0; k < 32; k++) {
        int j = k * 32 + lane;
        if (j < M_N && j != i) {
            float wbv = swb[j];
            float ac = __ldg(wac_row + j);
            float c  = __ldg(wc_row + j);
            nA += (ac < eps);
            nC += (c < eps);
            nB += (fmaxf(wbv, c) < eps);
        }
    }
    #pragma unroll
    for (int off = 16; off > 0; off >>= 1) {
        nA += __shfl_xor_sync(0xffffffffu, nA, off);
        nB += __shfl_xor_sync(0xffffffffu, nB, off);
        nC += __shfl_xor_sync(0xffffffffu, nC, off);
    }
    float wrow = g_psi[nC + 1] - g_psi[nA + 1] - g_psi[nB + 1];
    if (lane == 0) s_red[warp] = wrow;
    __syncthreads();
    if (threadIdx.x == 0)
        g_part[p * 256 + blockIdx.x] = s_red[0] + s_red[1] + s_red[2] + s_red[3];
}

// ---------------- deterministic final reduction ---------------------------------------------
__global__ void reduce_kernel(float* __restrict__ out) {
    __shared__ float sm[256];
    float s = 0.f;
    for (int idx = threadIdx.x; idx < N_PAIR * 255; idx += 256) {
        int p = idx / 255, b = idx % 255;
        s += g_part[p * 256 + b];
    }
    sm[threadIdx.x] = s;
    __syncthreads();
    if (threadIdx.x == 0) {
        float tot = 0.f;
        for (int k = 0; k < 256; k++) tot += sm[k];
        float psi3  = g_psi[3];
        float scale = 0.1f / 256.0f;               // BETA / (T*V*D)
        out[0] = scale * 0.25f * (28.0f * psi3 + tot / 1020.0f);
    }
}

extern "C" void kernel_launch(void* const* d_in, const int* in_sizes, int n_in,
                              void* d_out, int out_size) {
    const float* x = (const float*)d_in[0];
    float* out = (float*)d_out;
    static int attr_set = 0;
    if (!attr_set) {
        cudaFuncSetAttribute(te_kernel, cudaFuncAttributeMaxDynamicSharedMemorySize, 49152);
        attr_set = 1;
    }
    psi_kernel   <<<5, 256>>>();
    pack_kernel  <<<256, 256>>>(x);
    e_kernel     <<<dim3(16, 4),  256>>>();
    w_kernel     <<<dim3(128, 4), 256>>>();
    te_kernel    <<<dim3(255, 28), 128, 49152>>>();
    reduce_kernel<<<1, 256>>>(out);
}

// round 3
// speedup vs baseline: 2.1316x; 2.1316x over previous
#include <cuda_runtime.h>
#include <math.h>

// x[B=1024][T=8][V=4][D=8] fp32. Series (v,t) packed to g_xs[(v*8+t)][b][d].
// M = 1020. 28 pairs p = v*7+(t-1), t>=1; target series = (v,0).
#define B_N   1024
#define M_N   1020
#define RS    1024
#define N_PAIR 28

__device__ float g_xs [32 * B_N * 8];     // packed series (1 MB, L2-resident)
__device__ float g_WB [N_PAIR * M_N * RS];
__device__ float g_WC [4      * M_N * RS];
__device__ float g_WAC[4      * M_N * RS];
__device__ float g_part[N_PAIR * 128];
__device__ float g_psi[1040];

// ---------------- digamma table ------------------------------------------------------------
__global__ void psi_kernel() {
    int k = blockIdx.x * blockDim.x + threadIdx.x;
    if (k >= 1040) return;
    if (k == 0) { g_psi[0] = 0.f; return; }
    double s = 0.0;
    #pragma unroll
    for (int m = 0; m < 8; m++) s += 1.0 / (double)(k + m);
    double y = (double)k + 8.0;
    double inv = 1.0 / y, inv2 = inv * inv;
    double ps = log(y) - 0.5 * inv
              - inv2 * (1.0 / 12.0 - inv2 * (1.0 / 120.0 - inv2 * (1.0 / 252.0)));
    g_psi[k] = (float)(ps - s);
}

// ---------------- pack x -> per-series contiguous layout -----------------------------------
__global__ void pack_kernel(const float* __restrict__ x) {
    int o = blockIdx.x * 256 + threadIdx.x;       // float4 index, 65536 total
    int s = o >> 11;
    int r = o & 2047;
    int b = r >> 1, h = r & 1;
    int v = s >> 3, t = s & 7;
    ((float4*)g_xs)[o] = ((const float4*)x)[b * 64 + t * 8 + v * 2 + h];
}

// ---------------- fused E-tile + diagonal-window kernel ------------------------------------
// Block = (series s, triangular tile (ti<=tj)). Computes 68x68 E tile in smem (each cheb
// exactly once), reduces 4-diag window -> 64x64 W tile, writes direct + transposed
// (W matrices are symmetric).
#define TS  64
#define TH  68
#define SEP 72
#define SWP 65

__global__ void __launch_bounds__(256) ew_kernel() {
    __shared__ float sxi[TH * 8], sxj[TH * 8];
    __shared__ float sE[TH * SEP];
    __shared__ float sW[TS * SWP];

    int s = blockIdx.y;
    int t = s & 7, v = s >> 3;
    int tile = blockIdx.x;
    int ti = 0, rem = tile;
    while (rem >= 16 - ti) { rem -= 16 - ti; ti++; }
    int tj = ti + rem;
    int i0 = ti * TS, j0 = tj * TS;

    const float4* src = (const float4*)(g_xs + (size_t)s * (B_N * 8));
    for (int idx = threadIdx.x; idx < TH * 2; idx += 256) {
        int r = idx >> 1, h = idx & 1;
        int bi = min(i0 + r, B_N - 1);
        int bj = min(j0 + r, B_N - 1);
        ((float4*)sxi)[idx] = src[bi * 2 + h];
        ((float4*)sxj)[idx] = src[bj * 2 + h];
    }
    __syncthreads();

    int warp = threadIdx.x >> 5, lane = threadIdx.x & 31;
    // E tile: each warp takes 4-row groups; 17 groups cover 68 rows
    for (int g = warp; g < 17; g += 8) {
        int ib = g * 4;
        float4 xa[4][2];
        #pragma unroll
        for (int r = 0; r < 4; r++) {
            xa[r][0] = ((float4*)sxi)[(ib + r) * 2];
            xa[r][1] = ((float4*)sxi)[(ib + r) * 2 + 1];
        }
        for (int jj = lane; jj < TH; jj += 32) {
            float4 ya = ((float4*)sxj)[jj * 2];
            float4 yb = ((float4*)sxj)[jj * 2 + 1];
            #pragma unroll
            for (int r = 0; r < 4; r++) {
                float m;
                m =          fabsf(xa[r][0].x - ya.x);
                m = fmaxf(m, fabsf(xa[r][0].y - ya.y));
                m = fmaxf(m, fabsf(xa[r][0].z - ya.z));
                m = fmaxf(m, fabsf(xa[r][0].w - ya.w));
                m = fmaxf(m, fabsf(xa[r][1].x - yb.x));
                m = fmaxf(m, fabsf(xa[r][1].y - yb.y));
                m = fmaxf(m, fabsf(xa[r][1].z - yb.z));
                m = fmaxf(m, fabsf(xa[r][1].w - yb.w));
                sE[(ib + r) * SEP + jj] = m;
            }
        }
    }
    __syncthreads();

    // output stages: stage 0 -> WB (t>=1) or WC (t==0); stage 1 -> WAC (t==0 only)
    int nstage = (t == 0) ? 2 : 1;
    for (int st = 0; st < nstage; st++) {
        float* out;
        if (t == 0) out = (st == 0 ? g_WC : g_WAC) + (size_t)v * (M_N * RS);
        else        out = g_WB + (size_t)(v * 7 + t - 1) * (M_N * RS);

        int iiw = threadIdx.x >> 4;          // 0..15
        int jj4 = (threadIdx.x & 15) * 4;    // 0..60
        #pragma unroll
        for (int it = 0; it < 4; it++) {
            int ii = iiw + it * 16;
            float o[4];
            #pragma unroll
            for (int c = 0; c < 4; c++) {
                int jj = jj4 + c;
                float m;
                m =          sE[ ii      * SEP + jj    ];
                m = fmaxf(m, sE[(ii + 1) * SEP + jj + 1]);
                m = fmaxf(m, sE[(ii + 2) * SEP + jj + 2]);
                m = fmaxf(m, sE[(ii + 3) * SEP + jj + 3]);
                if (st == 1) m = fmaxf(m, sE[(ii + 4) * SEP + jj + 4]);
                o[c] = m;
                sW[ii * SWP + jj] = m;
            }
            int gi = i0 + ii;
            if (gi < M_N)
                *(float4*)(out + (size_t)gi * RS + j0 + jj4)
                    = make_float4(o[0], o[1], o[2], o[3]);
        }
        __syncthreads();
        if (ti != tj) {   // transposed write (symmetric matrix)
            int a  = threadIdx.x >> 4;        // row within tj tile
            int b4 = (threadIdx.x & 15) * 4;  // col within ti tile
            #pragma unroll
            for (int it = 0; it < 4; it++) {
                int aa = a + it * 16;
                int gj = j0 + aa;
                if (gj < M_N) {
                    float4 q = make_float4(
                        sW[(b4    ) * SWP + aa], sW[(b4 + 1) * SWP + aa],
                        sW[(b4 + 2) * SWP + aa], sW[(b4 + 3) * SWP + aa]);
                    *(float4*)(out + (size_t)gj * RS + i0 + b4) = q;
                }
            }
        }
        if (st + 1 < nstage) __syncthreads();
    }
}

// ---------------- per-row kNN(3) + counts; warp per row (round-1 version) ------------------
__device__ __forceinline__ void ins3(float v, float& t0, float& t1, float& t2) {
    if (v < t2) {
        if (v < t1) {
            t2 = t1;
            if (v < t0) { t1 = t0; t0 = v; } else t1 = v;
        } else t2 = v;
    }
}

__global__ void te_kernel() {
    int p = blockIdx.y;            // pair 0..27
    int v = p / 7;
    int warp = threadIdx.x >> 5, lane = threadIdx.x & 31;
    int i = blockIdx.x * 8 + warp;
    __shared__ float ws[8];
    float wrow = 0.f;
    if (i < M_N) {
        const float* wb  = g_WB  + (size_t)p * (M_N * RS) + (size_t)i * RS;
        const float* wac = g_WAC + (size_t)v * (M_N * RS) + (size_t)i * RS;
        const float* wc  = g_WC  + (size_t)v * (M_N * RS) + (size_t)i * RS;

        float t0 = 1e30f, t1 = 1e30f, t2 = 1e30f;
        for (int it = 0; it < 8; it++) {
            int j4 = it * 128 + lane * 4;
            if (j4 >= M_N) continue;
            float4 b4 = *(const float4*)(wb + j4);
            float4 a4 = *(const float4*)(wac + j4);
            const float* bb = (const float*)&b4;
            const float* aa = (const float*)&a4;
            #pragma unroll
            for (int c = 0; c < 4; c++) {
                int j = j4 + c;
                float dj = fmaxf(bb[c], aa[c]);
                if (j != i) ins3(dj, t0, t1, t2);
            }
        }
        #pragma unroll
        for (int off = 16; off > 0; off >>= 1) {
            float o0 = __shfl_xor_sync(0xffffffffu, t0, off);
            float o1 = __shfl_xor_sync(0xffffffffu, t1, off);
            float o2 = __shfl_xor_sync(0xffffffffu, t2, off);
            ins3(o0, t0, t1, t2); ins3(o1, t0, t1, t2); ins3(o2, t0, t1, t2);
        }
        float eps = t2;

        int nA = 0, nB = 0, nC = 0;
        for (int it = 0; it < 8; it++) {
            int j4 = it * 128 + lane * 4;
            if (j4 >= M_N) continue;
            float4 b4 = *(const float4*)(wb + j4);
            float4 a4 = *(const float4*)(wac + j4);
            float4 c4 = *(const float4*)(wc + j4);
            const float* bb = (const float*)&b4;
            const float* aa = (const float*)&a4;
            const float* cc = (const float*)&c4;
            #pragma unroll
            for (int c = 0; c < 4; c++) {
                int j = j4 + c;
                if (j == i) continue;
                float dc = cc[c];
                nC += (dc < eps);
                nA += (aa[c] < eps);
                nB += (fmaxf(bb[c], dc) < eps);
            }
        }
        #pragma unroll
        for (int off = 16; off > 0; off >>= 1) {
            nA += __shfl_xor_sync(0xffffffffu, nA, off);
            nB += __shfl_xor_sync(0xffffffffu, nB, off);
            nC += __shfl_xor_sync(0xffffffffu, nC, off);
        }
        wrow = g_psi[nC + 1] - g_psi[nA + 1] - g_psi[nB + 1];
    }
    if (lane == 0) ws[warp] = wrow;
    __syncthreads();
    if (threadIdx.x == 0) {
        float sum = 0.f;
        for (int k = 0; k < 8; k++) sum += ws[k];
        g_part[p * 128 + blockIdx.x] = sum;
    }
}

// ---------------- deterministic final reduction --------------------------------------------
__global__ void reduce_kernel(float* __restrict__ out) {
    __shared__ float sm[256];
    float s = 0.f;
    for (int idx = threadIdx.x; idx < N_PAIR * 128; idx += 256) s += g_part[idx];
    sm[threadIdx.x] = s;
    __syncthreads();
    if (threadIdx.x == 0) {
        float tot = 0.f;
        for (int k = 0; k < 256; k++) tot += sm[k];
        float psi3  = g_psi[3];
        float scale = 0.1f / 256.0f;               // BETA / (T*V*D)
        out[0] = scale * 0.25f * (28.0f * psi3 + tot / 1020.0f);
    }
}

extern "C" void kernel_launch(void* const* d_in, const int* in_sizes, int n_in,
                              void* d_out, int out_size) {
    const float* x = (const float*)d_in[0];
    float* out = (float*)d_out;
    psi_kernel   <<<5, 256>>>();
    pack_kernel  <<<256, 256>>>(x);
    ew_kernel    <<<dim3(136, 32), 256>>>();
    te_kernel    <<<dim3(128, 28), 256>>>();
    reduce_kernel<<<1, 256>>>(out);
}

// round 4
// speedup vs baseline: 2.1812x; 1.0233x over previous
#include <cuda_runtime.h>
#include <math.h>

// x[B=1024][T=8][V=4][D=8] fp32. Series s=(v*8+t) packed to g_xs[s][b][d].
// M = 1020. 28 pairs p = v*7+(t-1), t>=1; target series = (v,0).
#define B_N   1024
#define M_N   1020
#define RS    1024
#define N_PAIR 28
#define SENT  1e30f

__device__ float g_xs [32 * B_N * 8];
__device__ float g_WB [N_PAIR * M_N * RS];
__device__ float g_WC [4      * M_N * RS];
__device__ float g_WAC[4      * M_N * RS];
__device__ float g_part[N_PAIR * 128];
__device__ float g_psi[1040];

// ---------------- digamma table ------------------------------------------------------------
__global__ void psi_kernel() {
    int k = blockIdx.x * blockDim.x + threadIdx.x;
    if (k >= 1040) return;
    if (k == 0) { g_psi[0] = 0.f; return; }
    double s = 0.0;
    #pragma unroll
    for (int m = 0; m < 8; m++) s += 1.0 / (double)(k + m);
    double y = (double)k + 8.0;
    double inv = 1.0 / y, inv2 = inv * inv;
    double ps = log(y) - 0.5 * inv
              - inv2 * (1.0 / 12.0 - inv2 * (1.0 / 120.0 - inv2 * (1.0 / 252.0)));
    g_psi[k] = (float)(ps - s);
}

// ---------------- pack: coalesced read -> smem -> coalesced per-series write ---------------
#define PSTR 260   // padded float stride per b-row in smem
__global__ void pack_kernel(const float* __restrict__ x) {
    __shared__ float sm[16 * PSTR];
    int b0 = blockIdx.x * 16;
    for (int idx = threadIdx.x; idx < 1024; idx += 256) {
        int bl = idx >> 6, f = idx & 63;
        *(float4*)&sm[bl * PSTR + f * 4] = ((const float4*)x)[b0 * 64 + idx];
    }
    __syncthreads();
    #pragma unroll
    for (int k = 0; k < 4; k++) {
        int idx = threadIdx.x + k * 256;        // 0..1023
        int s = idx >> 5;                       // series: 32 float4 per series per block
        int q = idx & 31;
        int bl = q >> 1, h = q & 1;
        int t = s & 7, v = s >> 3;
        float4 val = *(float4*)&sm[bl * PSTR + (t * 8 + v * 2 + h) * 4];
        ((float4*)g_xs)[s * 2048 + (b0 + bl) * 2 + h] = val;
    }
}

// ---------------- fused E-tile + diagonal-window kernel ------------------------------------
#define TS  64
#define TH  68
#define SEP 72
#define SWP 65

__global__ void __launch_bounds__(256) ew_kernel() {
    __shared__ float sxi[TH * 8], sxj[TH * 8];
    __shared__ float sE[TH * SEP];
    __shared__ float sW[TS * SWP];

    int s = blockIdx.y;
    int t = s & 7, v = s >> 3;
    int tile = blockIdx.x;
    int ti = 0, rem = tile;
    while (rem >= 16 - ti) { rem -= 16 - ti; ti++; }
    int tj = ti + rem;
    int i0 = ti * TS, j0 = tj * TS;

    const float4* src = (const float4*)(g_xs + (size_t)s * (B_N * 8));
    for (int idx = threadIdx.x; idx < TH * 2; idx += 256) {
        int r = idx >> 1, h = idx & 1;
        int bi = min(i0 + r, B_N - 1);
        int bj = min(j0 + r, B_N - 1);
        ((float4*)sxi)[idx] = src[bi * 2 + h];
        ((float4*)sxj)[idx] = src[bj * 2 + h];
    }
    __syncthreads();

    int warp = threadIdx.x >> 5, lane = threadIdx.x & 31;
    // E tile: 34 groups of 2 rows over 8 warps
    for (int g = warp; g < 34; g += 8) {
        int ib = g * 2;
        float4 xa[2][2];
        #pragma unroll
        for (int r = 0; r < 2; r++) {
            xa[r][0] = ((float4*)sxi)[(ib + r) * 2];
            xa[r][1] = ((float4*)sxi)[(ib + r) * 2 + 1];
        }
        for (int jj = lane; jj < TH; jj += 32) {
            float4 ya = ((float4*)sxj)[jj * 2];
            float4 yb = ((float4*)sxj)[jj * 2 + 1];
            #pragma unroll
            for (int r = 0; r < 2; r++) {
                float m;
                m =          fabsf(xa[r][0].x - ya.x);
                m = fmaxf(m, fabsf(xa[r][0].y - ya.y));
                m = fmaxf(m, fabsf(xa[r][0].z - ya.z));
                m = fmaxf(m, fabsf(xa[r][0].w - ya.w));
                m = fmaxf(m, fabsf(xa[r][1].x - yb.x));
                m = fmaxf(m, fabsf(xa[r][1].y - yb.y));
                m = fmaxf(m, fabsf(xa[r][1].z - yb.z));
                m = fmaxf(m, fabsf(xa[r][1].w - yb.w));
                sE[(ib + r) * SEP + jj] = m;
            }
        }
    }
    __syncthreads();

    int nstage = (t == 0) ? 2 : 1;
    for (int st = 0; st < nstage; st++) {
        float* out;
        if (t == 0) out = (st == 0 ? g_WC : g_WAC) + (size_t)v * (M_N * RS);
        else        out = g_WB + (size_t)(v * 7 + t - 1) * (M_N * RS);

        int iiw = threadIdx.x >> 4;
        int jj4 = (threadIdx.x & 15) * 4;
        #pragma unroll
        for (int it = 0; it < 4; it++) {
            int ii = iiw + it * 16;
            float o[4];
            #pragma unroll
            for (int c = 0; c < 4; c++) {
                int jj = jj4 + c;
                float m;
                m =          sE[ ii      * SEP + jj    ];
                m = fmaxf(m, sE[(ii + 1) * SEP + jj + 1]);
                m = fmaxf(m, sE[(ii + 2) * SEP + jj + 2]);
                m = fmaxf(m, sE[(ii + 3) * SEP + jj + 3]);
                if (st == 1) m = fmaxf(m, sE[(ii + 4) * SEP + jj + 4]);
                o[c] = m;
                sW[ii * SWP + jj] = m;
            }
            int gi = i0 + ii;
            if (gi < M_N) {
                float4 q = (j0 + jj4 >= M_N)
                    ? make_float4(SENT, SENT, SENT, SENT)     // sentinel cols 1020..1023
                    : make_float4(o[0], o[1], o[2], o[3]);
                *(float4*)(out + (size_t)gi * RS + j0 + jj4) = q;
            }
        }
        __syncthreads();
        if (ti != tj) {   // transposed write (symmetric; cols here are < 960, no sentinel)
            int a  = threadIdx.x >> 4;
            int b4 = (threadIdx.x & 15) * 4;
            #pragma unroll
            for (int it = 0; it < 4; it++) {
                int aa = a + it * 16;
                int gj = j0 + aa;
                if (gj < M_N) {
                    float4 q = make_float4(
                        sW[(b4    ) * SWP + aa], sW[(b4 + 1) * SWP + aa],
                        sW[(b4 + 2) * SWP + aa], sW[(b4 + 3) * SWP + aa]);
                    *(float4*)(out + (size_t)gj * RS + i0 + b4) = q;
                }
            }
        }
        if (st + 1 < nstage) __syncthreads();
    }
}

// ---------------- branchless kNN + counts; warp per row ------------------------------------
// Self element included: dJ(i,i)=0 exactly => eps = 4th smallest incl. self = 3rd excl. self.
// Counts include self (+1 each since d(i,i)=0 < eps); folded via psi[n_true+1] = psi[n_total].
__device__ __forceinline__ void ins4(float v, float& t0, float& t1, float& t2, float& t3) {
    float n0 = fminf(t0, v);
    float n1 = fminf(t1, fmaxf(t0, v));
    float n2 = fminf(t2, fmaxf(t1, v));
    float n3 = fminf(t3, fmaxf(t2, v));
    t0 = n0; t1 = n1; t2 = n2; t3 = n3;
}

__global__ void te_kernel() {
    int p = blockIdx.y;
    int v = p / 7;
    int warp = threadIdx.x >> 5, lane = threadIdx.x & 31;
    int i = blockIdx.x * 8 + warp;
    __shared__ float ws[8];
    float wrow = 0.f;
    if (i < M_N) {
        const float* wb  = g_WB  + (size_t)p * (M_N * RS) + (size_t)i * RS;
        const float* wac = g_WAC + (size_t)v * (M_N * RS) + (size_t)i * RS;
        const float* wc  = g_WC  + (size_t)v * (M_N * RS) + (size_t)i * RS;

        // pass 1: top-4 of dJ = max(WAC, WB) over all 1024 cols (sentinels & self included)
        float t0 = SENT, t1 = SENT, t2 = SENT, t3 = SENT;
        #pragma unroll
        for (int it = 0; it < 8; it++) {
            int j4 = it * 128 + lane * 4;
            float4 b4 = *(const float4*)(wb + j4);
            float4 a4 = *(const float4*)(wac + j4);
            ins4(fmaxf(b4.x, a4.x), t0, t1, t2, t3);
            ins4(fmaxf(b4.y, a4.y), t0, t1, t2, t3);
            ins4(fmaxf(b4.z, a4.z), t0, t1, t2, t3);
            ins4(fmaxf(b4.w, a4.w), t0, t1, t2, t3);
        }
        #pragma unroll
        for (int off = 16; off > 0; off >>= 1) {
            float o0 = __shfl_xor_sync(0xffffffffu, t0, off);
            float o1 = __shfl_xor_sync(0xffffffffu, t1, off);
            float o2 = __shfl_xor_sync(0xffffffffu, t2, off);
            float o3 = __shfl_xor_sync(0xffffffffu, t3, off);
            ins4(o0, t0, t1, t2, t3); ins4(o1, t0, t1, t2, t3);
            ins4(o2, t0, t1, t2, t3); ins4(o3, t0, t1, t2, t3);
        }
        float eps = t3;

        // pass 2: counts over all 1024 cols (self contributes +1 to each; sentinels 0)
        int nA = 0, nB = 0, nC = 0;
        #pragma unroll
        for (int it = 0; it < 8; it++) {
            int j4 = it * 128 + lane * 4;
            float4 b4 = *(const float4*)(wb + j4);
            float4 a4 = *(const float4*)(wac + j4);
            float4 c4 = *(const float4*)(wc + j4);
            nA += (a4.x < eps) + (a4.y < eps) + (a4.z < eps) + (a4.w < eps);
            nC += (c4.x < eps) + (c4.y < eps) + (c4.z < eps) + (c4.w < eps);
            nB += (fmaxf(b4.x, c4.x) < eps) + (fmaxf(b4.y, c4.y) < eps)
                + (fmaxf(b4.z, c4.z) < eps) + (fmaxf(b4.w, c4.w) < eps);
        }
        #pragma unroll
        for (int off = 16; off > 0; off >>= 1) {
            nA += __shfl_xor_sync(0xffffffffu, nA, off);
            nB += __shfl_xor_sync(0xffffffffu, nB, off);
            nC += __shfl_xor_sync(0xffffffffu, nC, off);
        }
        // true count n = total - 1 (self); psi[n+1] = psi[total]
        wrow = g_psi[nC] - g_psi[nA] - g_psi[nB];
    }
    if (lane == 0) ws[warp] = wrow;
    __syncthreads();
    if (threadIdx.x == 0) {
        float sum = 0.f;
        for (int k = 0; k < 8; k++) sum += ws[k];
        g_part[p * 128 + blockIdx.x] = sum;
    }
}

// ---------------- deterministic final reduction --------------------------------------------
__global__ void reduce_kernel(float* __restrict__ out) {
    __shared__ float sm[256];
    float s = 0.f;
    for (int idx = threadIdx.x; idx < N_PAIR * 128; idx += 256) s += g_part[idx];
    sm[threadIdx.x] = s;
    __syncthreads();
    if (threadIdx.x == 0) {
        float tot = 0.f;
        for (int k = 0; k < 256; k++) tot += sm[k];
        float psi3  = g_psi[3];
        float scale = 0.1f / 256.0f;               // BETA / (T*V*D)
        out[0] = scale * 0.25f * (28.0f * psi3 + tot / 1020.0f);
    }
}

extern "C" void kernel_launch(void* const* d_in, const int* in_sizes, int n_in,
                              void* d_out, int out_size) {
    const float* x = (const float*)d_in[0];
    float* out = (float*)d_out;
    psi_kernel   <<<5, 256>>>();
    pack_kernel  <<<64, 256>>>(x);
    ew_kernel    <<<dim3(136, 32), 256>>>();
    te_kernel    <<<dim3(128, 28), 256>>>();
    reduce_kernel<<<1, 256>>>(out);
}

// round 6
// speedup vs baseline: 2.4421x; 1.1196x over previous
#include <cuda_runtime.h>
#include <math.h>

// x[B=1024][T=8][V=4][D=8] fp32. Series s=(v*8+t) packed to g_xs[s][b][d].
// M = 1020. 28 pairs p = v*7+(t-1), t>=1; target series = (v,0).
#define B_N   1024
#define M_N   1020
#define RS    1024
#define N_PAIR 28
#define SENT  1e30f

__device__ float g_xs [32 * B_N * 8];
__device__ float g_WB [N_PAIR * M_N * RS];
__device__ float g_WC [4      * M_N * RS];
__device__ float g_WAC[4      * M_N * RS];
__device__ float g_part[N_PAIR * 128];
__device__ float g_psi[1040];

// ---------------- digamma table ------------------------------------------------------------
__global__ void psi_kernel() {
    int k = blockIdx.x * blockDim.x + threadIdx.x;
    if (k >= 1040) return;
    if (k == 0) { g_psi[0] = 0.f; return; }
    double s = 0.0;
    #pragma unroll
    for (int m = 0; m < 8; m++) s += 1.0 / (double)(k + m);
    double y = (double)k + 8.0;
    double inv = 1.0 / y, inv2 = inv * inv;
    double ps = log(y) - 0.5 * inv
              - inv2 * (1.0 / 12.0 - inv2 * (1.0 / 120.0 - inv2 * (1.0 / 252.0)));
    g_psi[k] = (float)(ps - s);
}

// ---------------- pack: coalesced read -> smem -> coalesced per-series write ---------------
#define PSTR 260
__global__ void pack_kernel(const float* __restrict__ x) {
    __shared__ float sm[16 * PSTR];
    int b0 = blockIdx.x * 16;
    for (int idx = threadIdx.x; idx < 1024; idx += 256) {
        int bl = idx >> 6, f = idx & 63;
        *(float4*)&sm[bl * PSTR + f * 4] = ((const float4*)x)[b0 * 64 + idx];
    }
    __syncthreads();
    #pragma unroll
    for (int k = 0; k < 4; k++) {
        int idx = threadIdx.x + k * 256;
        int s = idx >> 5;
        int q = idx & 31;
        int bl = q >> 1, h = q & 1;
        int t = s & 7, v = s >> 3;
        float4 val = *(float4*)&sm[bl * PSTR + (t * 8 + v * 2 + h) * 4];
        ((float4*)g_xs)[s * 2048 + (b0 + bl) * 2 + h] = val;
    }
}

// ---------------- fused E-tile + diagonal-window kernel ------------------------------------
#define TS  64
#define TH  68
#define SEP 72
#define SWP 65

__global__ void __launch_bounds__(256) ew_kernel() {
    __shared__ float sxi[TH * 8], sxj[TH * 8];
    __shared__ float sE[TH * SEP];
    __shared__ float sW[TS * SWP];

    int s = blockIdx.y;
    int t = s & 7, v = s >> 3;
    int tile = blockIdx.x;
    int ti = 0, rem = tile;
    while (rem >= 16 - ti) { rem -= 16 - ti; ti++; }
    int tj = ti + rem;
    int i0 = ti * TS, j0 = tj * TS;

    const float4* src = (const float4*)(g_xs + (size_t)s * (B_N * 8));
    for (int idx = threadIdx.x; idx < TH * 2; idx += 256) {
        int r = idx >> 1, h = idx & 1;
        int bi = min(i0 + r, B_N - 1);
        int bj = min(j0 + r, B_N - 1);
        ((float4*)sxi)[idx] = src[bi * 2 + h];
        ((float4*)sxj)[idx] = src[bj * 2 + h];
    }
    __syncthreads();

    int warp = threadIdx.x >> 5, lane = threadIdx.x & 31;
    // E tile: 17 groups of 4 rows over 8 warps (ya/yb amortized over 4 chebs)
    for (int g = warp; g < 17; g += 8) {
        int ib = g * 4;
        float4 xa[4][2];
        #pragma unroll
        for (int r = 0; r < 4; r++) {
            xa[r][0] = ((float4*)sxi)[(ib + r) * 2];
            xa[r][1] = ((float4*)sxi)[(ib + r) * 2 + 1];
        }
        for (int jj = lane; jj < TH; jj += 32) {
            float4 ya = ((float4*)sxj)[jj * 2];
            float4 yb = ((float4*)sxj)[jj * 2 + 1];
            #pragma unroll
            for (int r = 0; r < 4; r++) {
                float m;
                m =          fabsf(xa[r][0].x - ya.x);
                m = fmaxf(m, fabsf(xa[r][0].y - ya.y));
                m = fmaxf(m, fabsf(xa[r][0].z - ya.z));
                m = fmaxf(m, fabsf(xa[r][0].w - ya.w));
                m = fmaxf(m, fabsf(xa[r][1].x - yb.x));
                m = fmaxf(m, fabsf(xa[r][1].y - yb.y));
                m = fmaxf(m, fabsf(xa[r][1].z - yb.z));
                m = fmaxf(m, fabsf(xa[r][1].w - yb.w));
                sE[(ib + r) * SEP + jj] = m;
            }
        }
    }
    __syncthreads();

    int nstage = (t == 0) ? 2 : 1;
    for (int st = 0; st < nstage; st++) {
        float* out;
        if (t == 0) out = (st == 0 ? g_WC : g_WAC) + (size_t)v * (M_N * RS);
        else        out = g_WB + (size_t)(v * 7 + t - 1) * (M_N * RS);

        int iiw = threadIdx.x >> 4;
        int jj4 = (threadIdx.x & 15) * 4;
        #pragma unroll
        for (int it = 0; it < 4; it++) {
            int ii = iiw + it * 16;
            float o[4];
            #pragma unroll
            for (int c = 0; c < 4; c++) {
                int jj = jj4 + c;
                float m;
                m =          sE[ ii      * SEP + jj    ];
                m = fmaxf(m, sE[(ii + 1) * SEP + jj + 1]);
                m = fmaxf(m, sE[(ii + 2) * SEP + jj + 2]);
                m = fmaxf(m, sE[(ii + 3) * SEP + jj + 3]);
                if (st == 1) m = fmaxf(m, sE[(ii + 4) * SEP + jj + 4]);
                o[c] = m;
                sW[ii * SWP + jj] = m;
            }
            int gi = i0 + ii;
            if (gi < M_N) {
                float4 q = (j0 + jj4 >= M_N)
                    ? make_float4(SENT, SENT, SENT, SENT)
                    : make_float4(o[0], o[1], o[2], o[3]);
                *(float4*)(out + (size_t)gi * RS + j0 + jj4) = q;
            }
        }
        __syncthreads();
        if (ti != tj) {
            int a  = threadIdx.x >> 4;
            int b4 = (threadIdx.x & 15) * 4;
            #pragma unroll
            for (int it = 0; it < 4; it++) {
                int aa = a + it * 16;
                int gj = j0 + aa;
                if (gj < M_N) {
                    float4 q = make_float4(
                        sW[(b4    ) * SWP + aa], sW[(b4 + 1) * SWP + aa],
                        sW[(b4 + 2) * SWP + aa], sW[(b4 + 3) * SWP + aa]);
                    *(float4*)(out + (size_t)gj * RS + i0 + b4) = q;
                }
            }
        }
        if (st + 1 < nstage) __syncthreads();
    }
}

// ---------------- branchless kNN + counts; occupancy-tuned ---------------------------------
__device__ __forceinline__ void ins4(float v, float& t0, float& t1, float& t2, float& t3) {
    float n0 = fminf(t0, v);
    float n1 = fminf(t1, fmaxf(t0, v));
    float n2 = fminf(t2, fmaxf(t1, v));
    float n3 = fminf(t3, fmaxf(t2, v));
    t0 = n0; t1 = n1; t2 = n2; t3 = n3;
}

__global__ void __launch_bounds__(256, 5) te_kernel() {
    int p = blockIdx.y;
    int v = p / 7;
    int warp = threadIdx.x >> 5, lane = threadIdx.x & 31;
    int i = blockIdx.x * 8 + warp;
    __shared__ float ws[8];
    float wrow = 0.f;
    if (i < M_N) {
        const float* wb  = g_WB  + (size_t)p * (M_N * RS) + (size_t)i * RS + lane * 4;
        const float* wac = g_WAC + (size_t)v * (M_N * RS) + (size_t)i * RS + lane * 4;
        const float* wc  = g_WC  + (size_t)v * (M_N * RS) + (size_t)i * RS + lane * 4;

        // pass 1: top-4 of dJ = max(WAC, WB); sentinels & self included (d(i,i)=0)
        float t0 = SENT, t1 = SENT, t2 = SENT, t3 = SENT;
        #pragma unroll 2
        for (int it = 0; it < 8; it++) {
            float4 b4 = *(const float4*)(wb + it * 128);
            float4 a4 = *(const float4*)(wac + it * 128);
            ins4(fmaxf(b4.x, a4.x), t0, t1, t2, t3);
            ins4(fmaxf(b4.y, a4.y), t0, t1, t2, t3);
            ins4(fmaxf(b4.z, a4.z), t0, t1, t2, t3);
            ins4(fmaxf(b4.w, a4.w), t0, t1, t2, t3);
        }
        #pragma unroll
        for (int off = 16; off > 0; off >>= 1) {
            float o0 = __shfl_xor_sync(0xffffffffu, t0, off);
            float o1 = __shfl_xor_sync(0xffffffffu, t1, off);
            float o2 = __shfl_xor_sync(0xffffffffu, t2, off);
            float o3 = __shfl_xor_sync(0xffffffffu, t3, off);
            ins4(o0, t0, t1, t2, t3); ins4(o1, t0, t1, t2, t3);
            ins4(o2, t0, t1, t2, t3); ins4(o3, t0, t1, t2, t3);
        }
        float eps = t3;   // 4th smallest incl. self == 3rd NN radius excl. self

        // pass 2: counts incl. self (+1 each); folded via psi[n+1] = psi[total]
        int nA = 0, nB = 0, nC = 0;
        #pragma unroll 2
        for (int it = 0; it < 8; it++) {
            float4 b4 = *(const float4*)(wb + it * 128);
            float4 a4 = *(const float4*)(wac + it * 128);
            float4 c4 = *(const float4*)(wc + it * 128);
            nA += (a4.x < eps) + (a4.y < eps) + (a4.z < eps) + (a4.w < eps);
            nC += (c4.x < eps) + (c4.y < eps) + (c4.z < eps) + (c4.w < eps);
            nB += (fmaxf(b4.x, c4.x) < eps) + (fmaxf(b4.y, c4.y) < eps)
                + (fmaxf(b4.z, c4.z) < eps) + (fmaxf(b4.w, c4.w) < eps);
        }
        #pragma unroll
        for (int off = 16; off > 0; off >>= 1) {
            nA += __shfl_xor_sync(0xffffffffu, nA, off);
            nB += __shfl_xor_sync(0xffffffffu, nB, off);
            nC += __shfl_xor_sync(0xffffffffu, nC, off);
        }
        wrow = g_psi[nC] - g_psi[nA] - g_psi[nB];
    }
    if (lane == 0) ws[warp] = wrow;
    __syncthreads();
    if (threadIdx.x == 0) {
        float sum = 0.f;
        for (int k = 0; k < 8; k++) sum += ws[k];
        g_part[p * 128 + blockIdx.x] = sum;
    }
}

// ---------------- deterministic final reduction --------------------------------------------
__global__ void reduce_kernel(float* __restrict__ out) {
    __shared__ float sm[256];
    float s = 0.f;
    for (int idx = threadIdx.x; idx < N_PAIR * 128; idx += 256) s += g_part[idx];
    sm[threadIdx.x] = s;
    __syncthreads();
    if (threadIdx.x == 0) {
        float tot = 0.f;
        for (int k = 0; k < 256; k++) tot += sm[k];
        float psi3  = g_psi[3];
        float scale = 0.1f / 256.0f;               // BETA / (T*V*D)
        out[0] = scale * 0.25f * (28.0f * psi3 + tot / 1020.0f);
    }
}

extern "C" void kernel_launch(void* const* d_in, const int* in_sizes, int n_in,
                              void* d_out, int out_size) {
    const float* x = (const float*)d_in[0];
    float* out = (float*)d_out;
    psi_kernel   <<<5, 256>>>();
    pack_kernel  <<<64, 256>>>(x);
    ew_kernel    <<<dim3(136, 32), 256>>>();
    te_kernel    <<<dim3(128, 28), 256>>>();
    reduce_kernel<<<1, 256>>>(out);
}

// round 7
// speedup vs baseline: 2.9000x; 1.1875x over previous
#include <cuda_runtime.h>
#include <math.h>

// x[B=1024][T=8][V=4][D=8] fp32. Series s=(v*8+t) packed to g_xs[s][b][d].
// M = 1020. 28 pairs p = v*7+(t-1), t>=1; target series = (v,0).
#define B_N   1024
#define M_N   1020
#define RS    1024
#define N_PAIR 28
#define SENT  1e30f

__device__ float g_xs [32 * B_N * 8];
__device__ float g_WB [N_PAIR * M_N * RS];
__device__ float g_WC [4      * M_N * RS];
__device__ float g_WAC[4      * M_N * RS];
__device__ float g_part[N_PAIR * 128];
__device__ float g_psi[1040];

// ---------------- digamma table ------------------------------------------------------------
__global__ void psi_kernel() {
    int k = blockIdx.x * blockDim.x + threadIdx.x;
    if (k >= 1040) return;
    if (k == 0) { g_psi[0] = 0.f; return; }
    double s = 0.0;
    #pragma unroll
    for (int m = 0; m < 8; m++) s += 1.0 / (double)(k + m);
    double y = (double)k + 8.0;
    double inv = 1.0 / y, inv2 = inv * inv;
    double ps = log(y) - 0.5 * inv
              - inv2 * (1.0 / 12.0 - inv2 * (1.0 / 120.0 - inv2 * (1.0 / 252.0)));
    g_psi[k] = (float)(ps - s);
}

// ---------------- pack: coalesced read -> smem -> coalesced per-series write ---------------
#define PSTR 260
__global__ void pack_kernel(const float* __restrict__ x) {
    __shared__ float sm[16 * PSTR];
    int b0 = blockIdx.x * 16;
    for (int idx = threadIdx.x; idx < 1024; idx += 256) {
        int bl = idx >> 6, f = idx & 63;
        *(float4*)&sm[bl * PSTR + f * 4] = ((const float4*)x)[b0 * 64 + idx];
    }
    __syncthreads();
    #pragma unroll
    for (int k = 0; k < 4; k++) {
        int idx = threadIdx.x + k * 256;
        int s = idx >> 5;
        int q = idx & 31;
        int bl = q >> 1, h = q & 1;
        int t = s & 7, v = s >> 3;
        float4 val = *(float4*)&sm[bl * PSTR + (t * 8 + v * 2 + h) * 4];
        ((float4*)g_xs)[s * 2048 + (b0 + bl) * 2 + h] = val;
    }
}

// ---------------- fused E-tile + diagonal-window kernel ------------------------------------
#define TS  64
#define TH  68
#define SEP 71   // odd stride: 2-way max conflicts in W-phase scalar reads
#define SWP 65

__global__ void __launch_bounds__(256) ew_kernel() {
    __shared__ float4 sxiA[TH], sxiB[TH], sxjA[TH], sxjB[TH];  // lo/hi split: coalesced LDS128
    __shared__ float sE[TH * SEP];
    __shared__ float sW[TS * SWP];

    int s = blockIdx.y;
    int t = s & 7, v = s >> 3;
    int tile = blockIdx.x;
    int ti = 0, rem = tile;
    while (rem >= 16 - ti) { rem -= 16 - ti; ti++; }
    int tj = ti + rem;
    int i0 = ti * TS, j0 = tj * TS;

    const float4* src = (const float4*)(g_xs + (size_t)s * (B_N * 8));
    if (threadIdx.x < TH) {
        int r  = threadIdx.x;
        int bi = min(i0 + r, B_N - 1);
        int bj = min(j0 + r, B_N - 1);
        sxiA[r] = src[bi * 2];     sxiB[r] = src[bi * 2 + 1];
        sxjA[r] = src[bj * 2];     sxjB[r] = src[bj * 2 + 1];
    }
    __syncthreads();

    int warp = threadIdx.x >> 5, lane = threadIdx.x & 31;
    // E tile: 17 groups of 4 rows over 8 warps
    for (int g = warp; g < 17; g += 8) {
        int ib = g * 4;
        float4 xa[4][2];
        #pragma unroll
        for (int r = 0; r < 4; r++) {
            xa[r][0] = sxiA[ib + r];
            xa[r][1] = sxiB[ib + r];
        }
        for (int jj = lane; jj < TH; jj += 32) {
            float4 ya = sxjA[jj];
            float4 yb = sxjB[jj];
            #pragma unroll
            for (int r = 0; r < 4; r++) {
                float m;
                m =          fabsf(xa[r][0].x - ya.x);
                m = fmaxf(m, fabsf(xa[r][0].y - ya.y));
                m = fmaxf(m, fabsf(xa[r][0].z - ya.z));
                m = fmaxf(m, fabsf(xa[r][0].w - ya.w));
                m = fmaxf(m, fabsf(xa[r][1].x - yb.x));
                m = fmaxf(m, fabsf(xa[r][1].y - yb.y));
                m = fmaxf(m, fabsf(xa[r][1].z - yb.z));
                m = fmaxf(m, fabsf(xa[r][1].w - yb.w));
                sE[(ib + r) * SEP + jj] = m;
            }
        }
    }
    __syncthreads();

    int nstage = (t == 0) ? 2 : 1;
    for (int st = 0; st < nstage; st++) {
        float* out;
        if (t == 0) out = (st == 0 ? g_WC : g_WAC) + (size_t)v * (M_N * RS);
        else        out = g_WB + (size_t)(v * 7 + t - 1) * (M_N * RS);

        int iiw = threadIdx.x >> 4;
        int jj4 = (threadIdx.x & 15) * 4;
        #pragma unroll
        for (int it = 0; it < 4; it++) {
            int ii = iiw + it * 16;
            float o[4];
            #pragma unroll
            for (int c = 0; c < 4; c++) {
                int jj = jj4 + c;
                float m;
                m =          sE[ ii      * SEP + jj    ];
                m = fmaxf(m, sE[(ii + 1) * SEP + jj + 1]);
                m = fmaxf(m, sE[(ii + 2) * SEP + jj + 2]);
                m = fmaxf(m, sE[(ii + 3) * SEP + jj + 3]);
                if (st == 1) m = fmaxf(m, sE[(ii + 4) * SEP + jj + 4]);
                o[c] = m;
                sW[ii * SWP + jj] = m;
            }
            int gi = i0 + ii;
            if (gi < M_N) {
                float4 q = (j0 + jj4 >= M_N)
                    ? make_float4(SENT, SENT, SENT, SENT)
                    : make_float4(o[0], o[1], o[2], o[3]);
                *(float4*)(out + (size_t)gi * RS + j0 + jj4) = q;
            }
        }
        __syncthreads();
        if (ti != tj) {
            int a  = threadIdx.x >> 4;
            int b4 = (threadIdx.x & 15) * 4;
            #pragma unroll
            for (int it = 0; it < 4; it++) {
                int aa = a + it * 16;
                int gj = j0 + aa;
                if (gj < M_N) {
                    float4 q = make_float4(
                        sW[(b4    ) * SWP + aa], sW[(b4 + 1) * SWP + aa],
                        sW[(b4 + 2) * SWP + aa], sW[(b4 + 3) * SWP + aa]);
                    *(float4*)(out + (size_t)gj * RS + i0 + b4) = q;
                }
            }
        }
        if (st + 1 < nstage) __syncthreads();
    }
}

// ---------------- branchless kNN + counts; occupancy-tuned ---------------------------------
__device__ __forceinline__ void ins4(float v, float& t0, float& t1, float& t2, float& t3) {
    float n0 = fminf(t0, v);
    float n1 = fminf(t1, fmaxf(t0, v));
    float n2 = fminf(t2, fmaxf(t1, v));
    float n3 = fminf(t3, fmaxf(t2, v));
    t0 = n0; t1 = n1; t2 = n2; t3 = n3;
}

__global__ void __launch_bounds__(256, 6) te_kernel() {
    int p = blockIdx.y;
    int v = p / 7;
    int warp = threadIdx.x >> 5, lane = threadIdx.x & 31;
    int i = blockIdx.x * 8 + warp;
    __shared__ float ws[8];
    float wrow = 0.f;
    if (i < M_N) {
        const float* wb  = g_WB  + (size_t)p * (M_N * RS) + (size_t)i * RS + lane * 4;
        const float* wac = g_WAC + (size_t)v * (M_N * RS) + (size_t)i * RS + lane * 4;
        const float* wc  = g_WC  + (size_t)v * (M_N * RS) + (size_t)i * RS + lane * 4;

        // pass 1: top-4 of dJ = max(WAC, WB); sentinels & self included (d(i,i)=0)
        float t0 = SENT, t1 = SENT, t2 = SENT, t3 = SENT;
        #pragma unroll 2
        for (int it = 0; it < 8; it++) {
            float4 b4 = *(const float4*)(wb + it * 128);
            float4 a4 = *(const float4*)(wac + it * 128);
            ins4(fmaxf(b4.x, a4.x), t0, t1, t2, t3);
            ins4(fmaxf(b4.y, a4.y), t0, t1, t2, t3);
            ins4(fmaxf(b4.z, a4.z), t0, t1, t2, t3);
            ins4(fmaxf(b4.w, a4.w), t0, t1, t2, t3);
        }
        #pragma unroll
        for (int off = 16; off > 0; off >>= 1) {
            float o0 = __shfl_xor_sync(0xffffffffu, t0, off);
            float o1 = __shfl_xor_sync(0xffffffffu, t1, off);
            float o2 = __shfl_xor_sync(0xffffffffu, t2, off);
            float o3 = __shfl_xor_sync(0xffffffffu, t3, off);
            ins4(o0, t0, t1, t2, t3); ins4(o1, t0, t1, t2, t3);
            ins4(o2, t0, t1, t2, t3); ins4(o3, t0, t1, t2, t3);
        }
        float eps = t3;   // 4th smallest incl. self == 3rd NN radius excl. self

        // pass 2: counts incl. self (+1 each); folded via psi[n+1] = psi[total]
        // max(b,c) < eps  <=>  (b < eps) && (c < eps)  -- exact, reuses the c predicate
        int nA = 0, nB = 0, nC = 0;
        #pragma unroll 2
        for (int it = 0; it < 8; it++) {
            float4 b4 = *(const float4*)(wb + it * 128);
            float4 a4 = *(const float4*)(wac + it * 128);
            float4 c4 = *(const float4*)(wc + it * 128);
            int pcx = (c4.x < eps), pcy = (c4.y < eps),
                pcz = (c4.z < eps), pcw = (c4.w < eps);
            nC += pcx + pcy + pcz + pcw;
            nA += (a4.x < eps) + (a4.y < eps) + (a4.z < eps) + (a4.w < eps);
            nB += (pcx && (b4.x < eps)) + (pcy && (b4.y < eps))
                + (pcz && (b4.z < eps)) + (pcw && (b4.w < eps));
        }
        #pragma unroll
        for (int off = 16; off > 0; off >>= 1) {
            nA += __shfl_xor_sync(0xffffffffu, nA, off);
            nB += __shfl_xor_sync(0xffffffffu, nB, off);
            nC += __shfl_xor_sync(0xffffffffu, nC, off);
        }
        wrow = g_psi[nC] - g_psi[nA] - g_psi[nB];
    }
    if (lane == 0) ws[warp] = wrow;
    __syncthreads();
    if (threadIdx.x == 0) {
        float sum = 0.f;
        for (int k = 0; k < 8; k++) sum += ws[k];
        g_part[p * 128 + blockIdx.x] = sum;
    }
}

// ---------------- deterministic final reduction --------------------------------------------
__global__ void reduce_kernel(float* __restrict__ out) {
    __shared__ float sm[256];
    float s = 0.f;
    for (int idx = threadIdx.x; idx < N_PAIR * 128; idx += 256) s += g_part[idx];
    sm[threadIdx.x] = s;
    __syncthreads();
    if (threadIdx.x == 0) {
        float tot = 0.f;
        for (int k = 0; k < 256; k++) tot += sm[k];
        float psi3  = g_psi[3];
        float scale = 0.1f / 256.0f;               // BETA / (T*V*D)
        out[0] = scale * 0.25f * (28.0f * psi3 + tot / 1020.0f);
    }
}

extern "C" void kernel_launch(void* const* d_in, const int* in_sizes, int n_in,
                              void* d_out, int out_size) {
    const float* x = (const float*)d_in[0];
    float* out = (float*)d_out;
    psi_kernel   <<<5, 256>>>();
    pack_kernel  <<<64, 256>>>(x);
    ew_kernel    <<<dim3(136, 32), 256>>>();
    te_kernel    <<<dim3(128, 28), 256>>>();
    reduce_kernel<<<1, 256>>>(out);
}